// round 6
// baseline (speedup 1.0000x reference)
#include <cuda_runtime.h>

#define S_LEN   2048
#define B_SZ    2
#define DM      1024
#define NH      16
#define HD      64
#define HK      1024            // NH*HD
#define MROWS   (B_SZ*S_LEN)    // 4096

// ---------------- scratch (static device arrays; no allocation) -------------
__device__ float g_q[B_SZ*NH*S_LEN*HD];   // (b,h,s,k) 16 MB
__device__ float g_k[B_SZ*NH*S_LEN*HD];
__device__ float g_v[B_SZ*NH*S_LEN*HD];
__device__ float g_o[MROWS*HK];           // (b,s,hk)  16 MB

// ---------------- tf32 helpers ----------------------------------------------
__device__ __forceinline__ unsigned f2tf32(float f) {
    unsigned r;
    asm("cvt.rna.tf32.f32 %0, %1;" : "=r"(r) : "f"(f));
    return r;
}

__device__ __forceinline__ void mma_tf32(float* c, const unsigned* a, const unsigned* b) {
    asm volatile(
        "mma.sync.aligned.m16n8k8.row.col.f32.tf32.tf32.f32 "
        "{%0,%1,%2,%3}, {%4,%5,%6,%7}, {%8,%9}, {%0,%1,%2,%3};\n"
        : "+f"(c[0]), "+f"(c[1]), "+f"(c[2]), "+f"(c[3])
        : "r"(a[0]), "r"(a[1]), "r"(a[2]), "r"(a[3]),
          "r"(b[0]), "r"(b[1]));
}

// =====================================================================
// TF32 GEMM, 128x128x16 tile, 256 threads (8 warps 4x2), double-buffered.
// (unchanged from R4)
// =====================================================================
#define GS 132   // smem row stride

#define GEMM_STAGE(buf) do {                                                  \
    As[buf][aCol+0][aRow]    = f2tf32(a0r.x);                                 \
    As[buf][aCol+1][aRow]    = f2tf32(a0r.y);                                 \
    As[buf][aCol+2][aRow]    = f2tf32(a0r.z);                                 \
    As[buf][aCol+3][aRow]    = f2tf32(a0r.w);                                 \
    As[buf][aCol+0][aRow+64] = f2tf32(a1r.x);                                 \
    As[buf][aCol+1][aRow+64] = f2tf32(a1r.y);                                 \
    As[buf][aCol+2][aRow+64] = f2tf32(a1r.z);                                 \
    As[buf][aCol+3][aRow+64] = f2tf32(a1r.w);                                 \
    Bs[buf][bRow][bCol+0]    = f2tf32(b0r.x);                                 \
    Bs[buf][bRow][bCol+1]    = f2tf32(b0r.y);                                 \
    Bs[buf][bRow][bCol+2]    = f2tf32(b0r.z);                                 \
    Bs[buf][bRow][bCol+3]    = f2tf32(b0r.w);                                 \
    Bs[buf][bRow+8][bCol+0]  = f2tf32(b1r.x);                                 \
    Bs[buf][bRow+8][bCol+1]  = f2tf32(b1r.y);                                 \
    Bs[buf][bRow+8][bCol+2]  = f2tf32(b1r.z);                                 \
    Bs[buf][bRow+8][bCol+3]  = f2tf32(b1r.w);                                 \
} while (0)

#define GEMM_MMA(buf) do {                                                    \
    _Pragma("unroll")                                                         \
    for (int ks = 0; ks < 2; ks++) {                                          \
        int kb = ks * 8;                                                      \
        unsigned af[2][4], bf[8][2];                                          \
        _Pragma("unroll")                                                     \
        for (int i = 0; i < 2; i++) {                                         \
            int mb = wm*32 + i*16;                                            \
            af[i][0] = As[buf][kb+tig  ][mb+g];                               \
            af[i][1] = As[buf][kb+tig  ][mb+g+8];                             \
            af[i][2] = As[buf][kb+tig+4][mb+g];                               \
            af[i][3] = As[buf][kb+tig+4][mb+g+8];                             \
        }                                                                     \
        _Pragma("unroll")                                                     \
        for (int j = 0; j < 8; j++) {                                         \
            int nb = wn*64 + j*8;                                             \
            bf[j][0] = Bs[buf][kb+tig  ][nb+g];                               \
            bf[j][1] = Bs[buf][kb+tig+4][nb+g];                               \
        }                                                                     \
        _Pragma("unroll")                                                     \
        for (int i = 0; i < 2; i++)                                           \
            _Pragma("unroll")                                                 \
            for (int j = 0; j < 8; j++)                                       \
                mma_tf32(acc[i][j], af[i], bf[j]);                            \
    }                                                                         \
} while (0)

__global__ __launch_bounds__(256, 2)
void qkv_gemm_tf32(const float* __restrict__ x,
                   const float* __restrict__ Wq, const float* __restrict__ bq,
                   const float* __restrict__ Wk, const float* __restrict__ bk,
                   const float* __restrict__ Wv, const float* __restrict__ bv)
{
    __shared__ unsigned As[2][16][GS];
    __shared__ unsigned Bs[2][16][GS];

    const float* W; const float* bias; float* out;
    int z = blockIdx.z;
    if (z == 0)      { W = Wq; bias = bq; out = g_q; }
    else if (z == 1) { W = Wk; bias = bk; out = g_k; }
    else             { W = Wv; bias = bv; out = g_v; }

    int tid  = threadIdx.x;
    int w    = tid >> 5, lane = tid & 31;
    int g    = lane >> 2, tig = lane & 3;
    int wm   = w & 3, wn = w >> 2;
    int m0   = blockIdx.y * 128, n0 = blockIdx.x * 128;

    int aRow = tid >> 2;
    int aCol = (tid & 3) * 4;
    int bRow = tid >> 5;
    int bCol = (tid & 31) * 4;

    const float* aPtr = x + (size_t)(m0 + aRow) * DM + aCol;
    const float* bPtr = W + (size_t)bRow * HK + n0 + bCol;

    float4 a0r = *(const float4*)aPtr;
    float4 a1r = *(const float4*)(aPtr + (size_t)64 * DM);
    float4 b0r = *(const float4*)bPtr;
    float4 b1r = *(const float4*)(bPtr + (size_t)8 * HK);

    float acc[2][8][4] = {};

    GEMM_STAGE(0);
    __syncthreads();

    for (int k0 = 0; k0 < DM; k0 += 16) {
        int cur = (k0 >> 4) & 1;
        bool more = (k0 + 16 < DM);
        if (more) {
            a0r = *(const float4*)(aPtr + (k0 + 16));
            a1r = *(const float4*)(aPtr + (size_t)64 * DM + (k0 + 16));
            b0r = *(const float4*)(bPtr + (size_t)(k0 + 16) * HK);
            b1r = *(const float4*)(bPtr + (size_t)(k0 + 24) * HK);
        }
        GEMM_MMA(cur);
        if (more) {
            if (cur) GEMM_STAGE(0); else GEMM_STAGE(1);
        }
        __syncthreads();
    }

    #pragma unroll
    for (int i = 0; i < 2; i++) {
        int r0m = m0 + wm*32 + i*16 + g;
        #pragma unroll
        for (int j = 0; j < 8; j++) {
            int n = n0 + wn*64 + j*8 + tig*2;
            int h = n >> 6, kd = n & 63;
            float bv0 = bias[n], bv1 = bias[n+1];
            int b0i = r0m >> 11, s0 = r0m & (S_LEN-1);
            size_t base0 = (((size_t)(b0i*NH + h) * S_LEN + s0) << 6) + kd;
            out[base0]     = acc[i][j][0] + bv0;
            out[base0 + 1] = acc[i][j][1] + bv1;
            int r1m = r0m + 8;
            int b1i = r1m >> 11, s1 = r1m & (S_LEN-1);
            size_t base1 = (((size_t)(b1i*NH + h) * S_LEN + s1) << 6) + kd;
            out[base1]     = acc[i][j][2] + bv0;
            out[base1 + 1] = acc[i][j][3] + bv1;
        }
    }
}

__global__ __launch_bounds__(256, 2)
void out_gemm_tf32(const float* __restrict__ Wo,
                   const float* __restrict__ bo,
                   float* __restrict__ C)
{
    __shared__ unsigned As[2][16][GS];
    __shared__ unsigned Bs[2][16][GS];

    int tid  = threadIdx.x;
    int w    = tid >> 5, lane = tid & 31;
    int g    = lane >> 2, tig = lane & 3;
    int wm   = w & 3, wn = w >> 2;
    int m0   = blockIdx.y * 128, n0 = blockIdx.x * 128;

    int aRow = tid >> 2;
    int aCol = (tid & 3) * 4;
    int bRow = tid >> 5;
    int bCol = (tid & 31) * 4;

    const float* aPtr = g_o + (size_t)(m0 + aRow) * HK + aCol;
    const float* bPtr = Wo + (size_t)bRow * DM + n0 + bCol;

    float4 a0r = *(const float4*)aPtr;
    float4 a1r = *(const float4*)(aPtr + (size_t)64 * HK);
    float4 b0r = *(const float4*)bPtr;
    float4 b1r = *(const float4*)(bPtr + (size_t)8 * DM);

    float acc[2][8][4] = {};

    GEMM_STAGE(0);
    __syncthreads();

    for (int k0 = 0; k0 < HK; k0 += 16) {
        int cur = (k0 >> 4) & 1;
        bool more = (k0 + 16 < HK);
        if (more) {
            a0r = *(const float4*)(aPtr + (k0 + 16));
            a1r = *(const float4*)(aPtr + (size_t)64 * HK + (k0 + 16));
            b0r = *(const float4*)(bPtr + (size_t)(k0 + 16) * DM);
            b1r = *(const float4*)(bPtr + (size_t)(k0 + 24) * DM);
        }
        GEMM_MMA(cur);
        if (more) {
            if (cur) GEMM_STAGE(0); else GEMM_STAGE(1);
        }
        __syncthreads();
    }

    #pragma unroll
    for (int i = 0; i < 2; i++) {
        int r0m = m0 + wm*32 + i*16 + g;
        #pragma unroll
        for (int j = 0; j < 8; j++) {
            int n = n0 + wn*64 + j*8 + tig*2;
            float bv0 = bo[n], bv1 = bo[n+1];
            float2 o0 = make_float2(acc[i][j][0] + bv0, acc[i][j][1] + bv1);
            float2 o1 = make_float2(acc[i][j][2] + bv0, acc[i][j][3] + bv1);
            *(float2*)&C[(size_t)r0m * DM + n]       = o0;
            *(float2*)&C[(size_t)(r0m+8) * DM + n]   = o1;
        }
    }
}

// =====================================================================
// Flash attention, tf32 MMA, software-pipelined K/V, smem Q fragments,
// exp2-domain softmax. keytile 64. 256 threads (8 warps x 16 q rows).
// Smem regions (unsigned words):
//   QA [8 w][8 kt][32 lane][4]  A-frags of Q (prescaled)   32 KB
//   KB [8 kt][8 nt][32 lane][2] B-frags of K               16 KB
//   VB [8 kt][8 nt][32 lane][2] B-frags of V               16 KB
//   PA [8 w][8 kt][32 lane][4]  A-frags of P (warp-priv)   32 KB
// total 96 KB -> 2 CTA/SM.
// =====================================================================
#define QA_OFF 0
#define KB_OFF 8192
#define VB_OFF 12288
#define PA_OFF 16384
#define ATTN_SMEM (24576 * 4)   // 96 KB
#define QSCALE 0.1803368801111204f   // 0.125 * log2(e)

__global__ __launch_bounds__(256, 2)
void attn_mma()
{
    extern __shared__ unsigned su[];
    unsigned* QA = su + QA_OFF;
    unsigned* KB = su + KB_OFF;
    unsigned* VB = su + VB_OFF;
    unsigned* PA = su + PA_OFF;

    int tid  = threadIdx.x;
    int w    = tid >> 5, lane = tid & 31;
    int g    = lane >> 2, tig = lane & 3;
    int bh   = blockIdx.y;
    int b    = bh >> 4, h = bh & 15;
    int q0   = blockIdx.x * 128;

    const float* qp = g_q + (size_t)bh * S_LEN * HD;
    const float* kp = g_k + (size_t)bh * S_LEN * HD;
    const float* vp = g_v + (size_t)bh * S_LEN * HD;

    // ---- stage Q as prescaled A-fragments into QA ----
    #pragma unroll
    for (int it = 0; it < 8; it++) {
        int linear = it*256 + tid;
        int r = linear >> 4, d0 = (linear & 15) * 4;
        float4 q4 = *(const float4*)&qp[(size_t)(q0 + r)*HD + d0];
        int wt = r >> 4, rr = r & 15;
        int gg = rr & 7, half = (rr >> 3) & 1;
        int kt = d0 >> 3, pair = (d0 >> 2) & 1;
        int reg = half + 2*pair;
        unsigned base = ((unsigned)(wt*8 + kt) << 7);
        QA[base + ((gg*4+0) << 2) + reg] = f2tf32(q4.x * QSCALE);
        QA[base + ((gg*4+1) << 2) + reg] = f2tf32(q4.y * QSCALE);
        QA[base + ((gg*4+2) << 2) + reg] = f2tf32(q4.z * QSCALE);
        QA[base + ((gg*4+3) << 2) + reg] = f2tf32(q4.w * QSCALE);
    }

    float o_acc[8][4] = {};
    float m0 = -1e30f, m1 = -1e30f, l0 = 0.f, l1 = 0.f;

    // ---- preload first K/V tile into registers ----
    float4 kreg[4], vreg[4];
    #pragma unroll
    for (int f = 0; f < 4; f++) {
        int linear = f*256 + tid;
        int j = linear >> 4, d0 = (linear & 15) * 4;
        kreg[f] = *(const float4*)&kp[(size_t)j*HD + d0];
        vreg[f] = *(const float4*)&vp[(size_t)j*HD + d0];
    }
    __syncthreads();   // QA visible

    for (int it = 0; it < S_LEN/64; it++) {
        // ---- STS K/V from registers into fragment layouts ----
        #pragma unroll
        for (int f = 0; f < 4; f++) {
            int linear = f*256 + tid;
            int j = linear >> 4, d0 = (linear & 15) * 4;
            {
                int kt = d0 >> 3, creg = (d0 >> 2) & 1;
                int nt = j >> 3, nin = j & 7;
                unsigned* dst = &KB[(((kt<<3)+nt)<<6) + (nin<<3) + creg];
                dst[0] = f2tf32(kreg[f].x); dst[2] = f2tf32(kreg[f].y);
                dst[4] = f2tf32(kreg[f].z); dst[6] = f2tf32(kreg[f].w);
            }
            {
                int ktv = j >> 3, kin = j & 7;
                int ntv = d0 >> 3;
                unsigned* dv = &VB[(((ktv<<3)+ntv)<<6) + (((d0&7)*4 + (kin&3))<<1) + (kin>>2)];
                dv[0]  = f2tf32(vreg[f].x); dv[8]  = f2tf32(vreg[f].y);
                dv[16] = f2tf32(vreg[f].z); dv[24] = f2tf32(vreg[f].w);
            }
        }
        __syncthreads();

        // ---- issue global loads for next tile (latency hidden by compute) ----
        if (it + 1 < S_LEN/64) {
            int t0n = (it + 1) * 64;
            #pragma unroll
            for (int f = 0; f < 4; f++) {
                int linear = f*256 + tid;
                int j = linear >> 4, d0 = (linear & 15) * 4;
                kreg[f] = *(const float4*)&kp[(size_t)(t0n + j)*HD + d0];
                vreg[f] = *(const float4*)&vp[(size_t)(t0n + j)*HD + d0];
            }
        }

        // ---- S = Q @ K^T (log2-domain logits) ----
        float s[8][4];
        #pragma unroll
        for (int nt = 0; nt < 8; nt++) { s[nt][0]=0.f; s[nt][1]=0.f; s[nt][2]=0.f; s[nt][3]=0.f; }
        #pragma unroll
        for (int kt = 0; kt < 8; kt++) {
            unsigned qa[4];
            *(uint4*)qa = *(const uint4*)&QA[(((unsigned)(w*8 + kt)) << 7) + (lane << 2)];
            #pragma unroll
            for (int nt = 0; nt < 8; nt++) {
                unsigned b2[2];
                *(uint2*)b2 = *(const uint2*)&KB[(((kt<<3)+nt)<<6) + (lane<<1)];
                mma_tf32(s[nt], qa, b2);
            }
        }

        // ---- online softmax (exp2 domain, quad-local) ----
        float mx0 = m0, mx1 = m1;
        #pragma unroll
        for (int nt = 0; nt < 8; nt++) {
            mx0 = fmaxf(mx0, fmaxf(s[nt][0], s[nt][1]));
            mx1 = fmaxf(mx1, fmaxf(s[nt][2], s[nt][3]));
        }
        mx0 = fmaxf(mx0, __shfl_xor_sync(0xffffffffu, mx0, 1));
        mx0 = fmaxf(mx0, __shfl_xor_sync(0xffffffffu, mx0, 2));
        mx1 = fmaxf(mx1, __shfl_xor_sync(0xffffffffu, mx1, 1));
        mx1 = fmaxf(mx1, __shfl_xor_sync(0xffffffffu, mx1, 2));

        float alpha0 = exp2f(m0 - mx0);
        float alpha1 = exp2f(m1 - mx1);
        m0 = mx0; m1 = mx1;

        float sum0 = 0.f, sum1 = 0.f;
        unsigned* paw = PA + w*1024;
        #pragma unroll
        for (int nt = 0; nt < 8; nt++) {
            float p00 = exp2f(s[nt][0] - mx0);
            float p01 = exp2f(s[nt][1] - mx0);
            float p10 = exp2f(s[nt][2] - mx1);
            float p11 = exp2f(s[nt][3] - mx1);
            sum0 += p00 + p01;
            sum1 += p10 + p11;
            int c0 = 2*tig;
            int regsel = (c0 < 4) ? 0 : 2;
            unsigned* base = &paw[((nt<<5) + 4*g + (c0&3)) * 4 + regsel];
            *(uint2*)base       = make_uint2(f2tf32(p00), f2tf32(p10));
            *(uint2*)(base + 4) = make_uint2(f2tf32(p01), f2tf32(p11));
        }
        sum0 += __shfl_xor_sync(0xffffffffu, sum0, 1);
        sum0 += __shfl_xor_sync(0xffffffffu, sum0, 2);
        sum1 += __shfl_xor_sync(0xffffffffu, sum1, 1);
        sum1 += __shfl_xor_sync(0xffffffffu, sum1, 2);
        l0 = l0*alpha0 + sum0;
        l1 = l1*alpha1 + sum1;

        #pragma unroll
        for (int nt = 0; nt < 8; nt++) {
            o_acc[nt][0] *= alpha0; o_acc[nt][1] *= alpha0;
            o_acc[nt][2] *= alpha1; o_acc[nt][3] *= alpha1;
        }
        __syncwarp();

        // ---- O += P @ V ----
        #pragma unroll
        for (int kt = 0; kt < 8; kt++) {
            unsigned pa[4];
            *(uint4*)pa = *(const uint4*)&paw[((kt<<5) + lane) * 4];
            #pragma unroll
            for (int nt = 0; nt < 8; nt++) {
                unsigned b2[2];
                *(uint2*)b2 = *(const uint2*)&VB[(((kt<<3)+nt)<<6) + (lane<<1)];
                mma_tf32(o_acc[nt], pa, b2);
            }
        }
        __syncthreads();   // KB/VB free for next iteration's STS
    }

    // ---- epilogue ----
    float inv0 = 1.0f / l0, inv1 = 1.0f / l1;
    int r0 = q0 + 16*w + g, r1 = r0 + 8;
    #pragma unroll
    for (int nt = 0; nt < 8; nt++) {
        int c = nt*8 + 2*tig;
        *(float2*)&g_o[(size_t)(b*S_LEN + r0)*HK + h*64 + c] =
            make_float2(o_acc[nt][0]*inv0, o_acc[nt][1]*inv0);
        *(float2*)&g_o[(size_t)(b*S_LEN + r1)*HK + h*64 + c] =
            make_float2(o_acc[nt][2]*inv1, o_acc[nt][3]*inv1);
    }
}

// =====================================================================
extern "C" void kernel_launch(void* const* d_in, const int* in_sizes, int n_in,
                              void* d_out, int out_size)
{
    (void)in_sizes; (void)n_in; (void)out_size;
    const float* x  = (const float*)d_in[0];
    const float* Wq = (const float*)d_in[1];
    const float* bq = (const float*)d_in[2];
    const float* Wk = (const float*)d_in[3];
    const float* bk = (const float*)d_in[4];
    const float* Wv = (const float*)d_in[5];
    const float* bv = (const float*)d_in[6];
    const float* Wo = (const float*)d_in[7];
    const float* bo = (const float*)d_in[8];
    float* out = (float*)d_out;

    qkv_gemm_tf32<<<dim3(HK/128, MROWS/128, 3), 256>>>(x, Wq, bq, Wk, bk, Wv, bv);

    cudaFuncSetAttribute(attn_mma, cudaFuncAttributeMaxDynamicSharedMemorySize, ATTN_SMEM);
    attn_mma<<<dim3(S_LEN/128, B_SZ*NH), 256, ATTN_SMEM>>>();

    out_gemm_tf32<<<dim3(DM/128, MROWS/128), 256>>>(Wo, bo, out);
}

// round 7
// speedup vs baseline: 1.1184x; 1.1184x over previous
#include <cuda_runtime.h>

#define S_LEN   2048
#define B_SZ    2
#define DM      1024
#define NH      16
#define HD      64
#define HK      1024            // NH*HD
#define MROWS   (B_SZ*S_LEN)    // 4096

// ---------------- scratch (static device arrays; no allocation) -------------
__device__ float g_q[B_SZ*NH*S_LEN*HD];   // (b,h,s,k) 16 MB
__device__ float g_k[B_SZ*NH*S_LEN*HD];
__device__ float g_v[B_SZ*NH*S_LEN*HD];
__device__ float g_o[MROWS*HK];           // (b,s,hk)  16 MB

// ---------------- tf32 helpers ----------------------------------------------
__device__ __forceinline__ unsigned f2tf32(float f) {
    unsigned r;
    asm("cvt.rna.tf32.f32 %0, %1;" : "=r"(r) : "f"(f));
    return r;
}

__device__ __forceinline__ void mma_tf32(float* c, const unsigned* a, const unsigned* b) {
    asm volatile(
        "mma.sync.aligned.m16n8k8.row.col.f32.tf32.tf32.f32 "
        "{%0,%1,%2,%3}, {%4,%5,%6,%7}, {%8,%9}, {%0,%1,%2,%3};\n"
        : "+f"(c[0]), "+f"(c[1]), "+f"(c[2]), "+f"(c[3])
        : "r"(a[0]), "r"(a[1]), "r"(a[2]), "r"(a[3]),
          "r"(b[0]), "r"(b[1]));
}

// =====================================================================
// TF32 GEMM, CTA tile 128x128x16, 128 threads (4 warps 2x2),
// warp tile 64x64 (4 m16 x 8 n8) -> 2KB smem frags per 16 MMAs.
// Double-buffered smem.
// =====================================================================
#define GS 132   // smem row stride (unsigned words)

// staging: A slab 128x16, B slab 16x128; 4 float4 per thread each.
#define GEMM_STAGE64(buf) do {                                                \
    _Pragma("unroll")                                                         \
    for (int p = 0; p < 4; p++) {                                             \
        int la = p*128 + tid;                                                 \
        int row = la >> 2, kc = (la & 3) * 4;                                 \
        As[buf][kc+0][row] = f2tf32(av[p].x);                                 \
        As[buf][kc+1][row] = f2tf32(av[p].y);                                 \
        As[buf][kc+2][row] = f2tf32(av[p].z);                                 \
        As[buf][kc+3][row] = f2tf32(av[p].w);                                 \
        int lb = p*128 + tid;                                                 \
        int kr = lb >> 5, nc = (lb & 31) * 4;                                 \
        Bs[buf][kr][nc+0] = f2tf32(bvv[p].x);                                 \
        Bs[buf][kr][nc+1] = f2tf32(bvv[p].y);                                 \
        Bs[buf][kr][nc+2] = f2tf32(bvv[p].z);                                 \
        Bs[buf][kr][nc+3] = f2tf32(bvv[p].w);                                 \
    }                                                                         \
} while (0)

#define GEMM_LOAD64(kbase) do {                                               \
    _Pragma("unroll")                                                         \
    for (int p = 0; p < 4; p++) {                                             \
        int la = p*128 + tid;                                                 \
        av[p]  = *(const float4*)&aP[(size_t)(la >> 2) * KROW + (kbase) + (la & 3) * 4]; \
        int lb = p*128 + tid;                                                 \
        bvv[p] = *(const float4*)&bP[(size_t)((kbase) + (lb >> 5)) * NROW + (lb & 31) * 4]; \
    }                                                                         \
} while (0)

#define GEMM_MMA64(buf) do {                                                  \
    _Pragma("unroll")                                                         \
    for (int ks = 0; ks < 2; ks++) {                                          \
        int kb = ks * 8;                                                      \
        unsigned af[4][4], bf[8][2];                                          \
        _Pragma("unroll")                                                     \
        for (int i = 0; i < 4; i++) {                                         \
            int mb = wm*64 + i*16;                                            \
            af[i][0] = As[buf][kb+tig  ][mb+g];                               \
            af[i][1] = As[buf][kb+tig  ][mb+g+8];                             \
            af[i][2] = As[buf][kb+tig+4][mb+g];                               \
            af[i][3] = As[buf][kb+tig+4][mb+g+8];                             \
        }                                                                     \
        _Pragma("unroll")                                                     \
        for (int j = 0; j < 8; j++) {                                         \
            int nb = wn*64 + j*8;                                             \
            bf[j][0] = Bs[buf][kb+tig  ][nb+g];                               \
            bf[j][1] = Bs[buf][kb+tig+4][nb+g];                               \
        }                                                                     \
        _Pragma("unroll")                                                     \
        for (int i = 0; i < 4; i++)                                           \
            _Pragma("unroll")                                                 \
            for (int j = 0; j < 8; j++)                                       \
                mma_tf32(acc[i][j], af[i], bf[j]);                            \
    }                                                                         \
} while (0)

__global__ __launch_bounds__(128, 2)
void qkv_gemm_tf32(const float* __restrict__ x,
                   const float* __restrict__ Wq, const float* __restrict__ bq,
                   const float* __restrict__ Wk, const float* __restrict__ bk,
                   const float* __restrict__ Wv, const float* __restrict__ bv)
{
    __shared__ unsigned As[2][16][GS];
    __shared__ unsigned Bs[2][16][GS];

    const float* W; const float* bias; float* out;
    int z = blockIdx.z;
    if (z == 0)      { W = Wq; bias = bq; out = g_q; }
    else if (z == 1) { W = Wk; bias = bk; out = g_k; }
    else             { W = Wv; bias = bv; out = g_v; }

    const int KROW = DM, NROW = HK;
    int tid  = threadIdx.x;
    int w    = tid >> 5, lane = tid & 31;
    int g    = lane >> 2, tig = lane & 3;
    int wm   = w & 1, wn = w >> 1;
    int m0   = blockIdx.y * 128, n0 = blockIdx.x * 128;

    const float* aP = x + (size_t)m0 * KROW;
    const float* bP = W + n0;

    float4 av[4], bvv[4];
    float acc[4][8][4] = {};

    GEMM_LOAD64(0);
    GEMM_STAGE64(0);
    __syncthreads();

    for (int k0 = 0; k0 < DM; k0 += 16) {
        int cur = (k0 >> 4) & 1;
        bool more = (k0 + 16 < DM);
        if (more) GEMM_LOAD64(k0 + 16);
        GEMM_MMA64(cur);
        if (more) {
            if (cur) GEMM_STAGE64(0); else GEMM_STAGE64(1);
        }
        __syncthreads();
    }

    #pragma unroll
    for (int i = 0; i < 4; i++) {
        int r0m = m0 + wm*64 + i*16 + g;
        #pragma unroll
        for (int j = 0; j < 8; j++) {
            int n = n0 + wn*64 + j*8 + tig*2;
            int h = n >> 6, kd = n & 63;
            float bv0 = bias[n], bv1 = bias[n+1];
            int b0i = r0m >> 11, s0 = r0m & (S_LEN-1);
            size_t base0 = (((size_t)(b0i*NH + h) * S_LEN + s0) << 6) + kd;
            out[base0]     = acc[i][j][0] + bv0;
            out[base0 + 1] = acc[i][j][1] + bv1;
            int r1m = r0m + 8;
            int b1i = r1m >> 11, s1 = r1m & (S_LEN-1);
            size_t base1 = (((size_t)(b1i*NH + h) * S_LEN + s1) << 6) + kd;
            out[base1]     = acc[i][j][2] + bv0;
            out[base1 + 1] = acc[i][j][3] + bv1;
        }
    }
}

__global__ __launch_bounds__(128, 2)
void out_gemm_tf32(const float* __restrict__ Wo,
                   const float* __restrict__ bo,
                   float* __restrict__ C)
{
    __shared__ unsigned As[2][16][GS];
    __shared__ unsigned Bs[2][16][GS];

    const int KROW = HK, NROW = DM;
    int tid  = threadIdx.x;
    int w    = tid >> 5, lane = tid & 31;
    int g    = lane >> 2, tig = lane & 3;
    int wm   = w & 1, wn = w >> 1;
    int m0   = blockIdx.y * 128, n0 = blockIdx.x * 128;

    const float* aP = g_o + (size_t)m0 * KROW;
    const float* bP = Wo + n0;

    float4 av[4], bvv[4];
    float acc[4][8][4] = {};

    GEMM_LOAD64(0);
    GEMM_STAGE64(0);
    __syncthreads();

    for (int k0 = 0; k0 < HK; k0 += 16) {
        int cur = (k0 >> 4) & 1;
        bool more = (k0 + 16 < HK);
        if (more) GEMM_LOAD64(k0 + 16);
        GEMM_MMA64(cur);
        if (more) {
            if (cur) GEMM_STAGE64(0); else GEMM_STAGE64(1);
        }
        __syncthreads();
    }

    #pragma unroll
    for (int i = 0; i < 4; i++) {
        int r0m = m0 + wm*64 + i*16 + g;
        #pragma unroll
        for (int j = 0; j < 8; j++) {
            int n = n0 + wn*64 + j*8 + tig*2;
            float bv0 = bo[n], bv1 = bo[n+1];
            float2 o0 = make_float2(acc[i][j][0] + bv0, acc[i][j][1] + bv1);
            float2 o1 = make_float2(acc[i][j][2] + bv0, acc[i][j][3] + bv1);
            *(float2*)&C[(size_t)r0m * DM + n]       = o0;
            *(float2*)&C[(size_t)(r0m+8) * DM + n]   = o1;
        }
    }
}

// =====================================================================
// Flash attention on tf32 tensor cores (R4 known-good version).
// keytile 64, smem 64 KB -> 2 CTA/SM. 256 threads (8 warps x 16 q rows).
// =====================================================================
#define ATTN_SMEM (16384 * 4)   // 64 KB

__global__ __launch_bounds__(256, 2)
void attn_mma()
{
    extern __shared__ unsigned su[];
    unsigned* KB = su;            // 4096
    unsigned* VB = su + 4096;     // 4096
    unsigned* PA = su + 8192;     // 8192

    int tid  = threadIdx.x;
    int w    = tid >> 5, lane = tid & 31;
    int g    = lane >> 2, tig = lane & 3;
    int bh   = blockIdx.y;
    int b    = bh >> 4, h = bh & 15;
    int q0   = blockIdx.x * 128;

    const float* qp = g_q + (size_t)bh * S_LEN * HD;
    const float* kp = g_k + (size_t)bh * S_LEN * HD;
    const float* vp = g_v + (size_t)bh * S_LEN * HD;

    float* Qs = (float*)su;
    #pragma unroll
    for (int it = 0; it < 8; it++) {
        int linear = it*256 + tid;
        int j = linear >> 4, d0 = (linear & 15) * 4;
        *(float4*)&Qs[j*64 + d0] = *(const float4*)&qp[(size_t)(q0 + j)*HD + d0];
    }
    __syncthreads();
    unsigned qf[8][4];
    #pragma unroll
    for (int kt = 0; kt < 8; kt++) {
        qf[kt][0] = f2tf32(Qs[(16*w+g  )*64 + kt*8 + tig  ]);
        qf[kt][1] = f2tf32(Qs[(16*w+g+8)*64 + kt*8 + tig  ]);
        qf[kt][2] = f2tf32(Qs[(16*w+g  )*64 + kt*8 + tig+4]);
        qf[kt][3] = f2tf32(Qs[(16*w+g+8)*64 + kt*8 + tig+4]);
    }
    __syncthreads();

    float o_acc[8][4] = {};
    float m0 = -1e30f, m1 = -1e30f, l0 = 0.f, l1 = 0.f;

    for (int t0 = 0; t0 < S_LEN; t0 += 64) {
        #pragma unroll
        for (int it = 0; it < 4; it++) {
            int linear = it*256 + tid;
            int j = linear >> 4, d0 = (linear & 15) * 4;
            float4 kv = *(const float4*)&kp[(size_t)(t0+j)*HD + d0];
            {
                int kt = d0 >> 3, creg = (d0 >> 2) & 1;
                int nt = j >> 3, nin = j & 7;
                unsigned* dst = &KB[(((kt<<3)+nt)<<6) + (nin<<3) + creg];
                dst[0] = f2tf32(kv.x); dst[2] = f2tf32(kv.y);
                dst[4] = f2tf32(kv.z); dst[6] = f2tf32(kv.w);
            }
            float4 vv = *(const float4*)&vp[(size_t)(t0+j)*HD + d0];
            {
                int ktv = j >> 3, kin = j & 7;
                int ntv = d0 >> 3;
                unsigned* dv = &VB[(((ktv<<3)+ntv)<<6) + (((d0&7)*4 + (kin&3))<<1) + (kin>>2)];
                dv[0]  = f2tf32(vv.x); dv[8]  = f2tf32(vv.y);
                dv[16] = f2tf32(vv.z); dv[24] = f2tf32(vv.w);
            }
        }
        __syncthreads();

        float s[8][4];
        #pragma unroll
        for (int nt = 0; nt < 8; nt++) { s[nt][0]=0.f; s[nt][1]=0.f; s[nt][2]=0.f; s[nt][3]=0.f; }
        #pragma unroll
        for (int kt = 0; kt < 8; kt++) {
            #pragma unroll
            for (int nt = 0; nt < 8; nt++) {
                unsigned b2[2];
                *(uint2*)b2 = *(const uint2*)&KB[(((kt<<3)+nt)<<6) + (lane<<1)];
                mma_tf32(s[nt], qf[kt], b2);
            }
        }

        float mx0 = m0, mx1 = m1;
        #pragma unroll
        for (int nt = 0; nt < 8; nt++) {
            mx0 = fmaxf(mx0, fmaxf(s[nt][0], s[nt][1]) * 0.125f);
            mx1 = fmaxf(mx1, fmaxf(s[nt][2], s[nt][3]) * 0.125f);
        }
        mx0 = fmaxf(mx0, __shfl_xor_sync(0xffffffffu, mx0, 1));
        mx0 = fmaxf(mx0, __shfl_xor_sync(0xffffffffu, mx0, 2));
        mx1 = fmaxf(mx1, __shfl_xor_sync(0xffffffffu, mx1, 1));
        mx1 = fmaxf(mx1, __shfl_xor_sync(0xffffffffu, mx1, 2));

        float alpha0 = __expf(m0 - mx0);
        float alpha1 = __expf(m1 - mx1);
        m0 = mx0; m1 = mx1;

        float sum0 = 0.f, sum1 = 0.f;
        unsigned* paw = PA + w*1024;
        #pragma unroll
        for (int nt = 0; nt < 8; nt++) {
            float p00 = __expf(s[nt][0]*0.125f - mx0);
            float p01 = __expf(s[nt][1]*0.125f - mx0);
            float p10 = __expf(s[nt][2]*0.125f - mx1);
            float p11 = __expf(s[nt][3]*0.125f - mx1);
            sum0 += p00 + p01;
            sum1 += p10 + p11;
            int c0 = 2*tig;
            int regsel = (c0 < 4) ? 0 : 2;
            unsigned* base = &paw[((nt<<5) + 4*g + (c0&3)) * 4 + regsel];
            *(uint2*)base       = make_uint2(f2tf32(p00), f2tf32(p10));
            *(uint2*)(base + 4) = make_uint2(f2tf32(p01), f2tf32(p11));
        }
        sum0 += __shfl_xor_sync(0xffffffffu, sum0, 1);
        sum0 += __shfl_xor_sync(0xffffffffu, sum0, 2);
        sum1 += __shfl_xor_sync(0xffffffffu, sum1, 1);
        sum1 += __shfl_xor_sync(0xffffffffu, sum1, 2);
        l0 = l0*alpha0 + sum0;
        l1 = l1*alpha1 + sum1;

        #pragma unroll
        for (int nt = 0; nt < 8; nt++) {
            o_acc[nt][0] *= alpha0; o_acc[nt][1] *= alpha0;
            o_acc[nt][2] *= alpha1; o_acc[nt][3] *= alpha1;
        }
        __syncwarp();

        #pragma unroll
        for (int kt = 0; kt < 8; kt++) {
            unsigned pa[4];
            *(uint4*)pa = *(const uint4*)&paw[((kt<<5) + lane) * 4];
            #pragma unroll
            for (int nt = 0; nt < 8; nt++) {
                unsigned b2[2];
                *(uint2*)b2 = *(const uint2*)&VB[(((kt<<3)+nt)<<6) + (lane<<1)];
                mma_tf32(o_acc[nt], pa, b2);
            }
        }
        __syncthreads();
    }

    float inv0 = 1.0f / l0, inv1 = 1.0f / l1;
    int r0 = q0 + 16*w + g, r1 = r0 + 8;
    #pragma unroll
    for (int nt = 0; nt < 8; nt++) {
        int c = nt*8 + 2*tig;
        *(float2*)&g_o[(size_t)(b*S_LEN + r0)*HK + h*64 + c] =
            make_float2(o_acc[nt][0]*inv0, o_acc[nt][1]*inv0);
        *(float2*)&g_o[(size_t)(b*S_LEN + r1)*HK + h*64 + c] =
            make_float2(o_acc[nt][2]*inv1, o_acc[nt][3]*inv1);
    }
}

// =====================================================================
extern "C" void kernel_launch(void* const* d_in, const int* in_sizes, int n_in,
                              void* d_out, int out_size)
{
    (void)in_sizes; (void)n_in; (void)out_size;
    const float* x  = (const float*)d_in[0];
    const float* Wq = (const float*)d_in[1];
    const float* bq = (const float*)d_in[2];
    const float* Wk = (const float*)d_in[3];
    const float* bk = (const float*)d_in[4];
    const float* Wv = (const float*)d_in[5];
    const float* bv = (const float*)d_in[6];
    const float* Wo = (const float*)d_in[7];
    const float* bo = (const float*)d_in[8];
    float* out = (float*)d_out;

    qkv_gemm_tf32<<<dim3(HK/128, MROWS/128, 3), 128>>>(x, Wq, bq, Wk, bk, Wv, bv);

    cudaFuncSetAttribute(attn_mma, cudaFuncAttributeMaxDynamicSharedMemorySize, ATTN_SMEM);
    attn_mma<<<dim3(S_LEN/128, B_SZ*NH), 256, ATTN_SMEM>>>();

    out_gemm_tf32<<<dim3(DM/128, MROWS/128), 128>>>(Wo, bo, out);
}